// round 10
// baseline (speedup 1.0000x reference)
#include <cuda_runtime.h>
#include <math.h>
#include <stdint.h>

#define BB   2
#define SS   2048
#define DD   1024
#define HH   16
#define HDIM 64
#define FFND 2048
#define NE   8
#define CAPN 1280
#define TT   (BB*SS)
#define NS   (TT*2)

// ---------------- scratch (device globals; no allocations) ----------------
__device__ float g_xn  [TT*DD];
__device__ float g_qkv [TT*3*DD];
__device__ float g_attn[TT*DD];
__device__ float g_x1  [TT*DD];
__device__ float g_xn2 [TT*DD];
__device__ int   g_fe  [NS];
__device__ float g_fg  [NS];
__device__ int   g_cnt [NE];
__device__ int   g_esl [NE*NS];
__device__ float g_egt [NE*NS];
__device__ int   g_dtok[NE*CAPN];
__device__ int   g_srow[NS];
__device__ float g_xe  [NE*CAPN*DD];
__device__ float g_h   [NE*CAPN*FFND];
__device__ float g_ye  [NE*CAPN*DD];

// ---------------- helpers ----------------
__device__ __forceinline__ uint32_t f2tf32(float x) {
    uint32_t y;
    asm("cvt.rna.tf32.f32 %0, %1;" : "=r"(y) : "f"(x));
    return y;
}
__device__ __forceinline__ float tf32r(float x) {
    return __uint_as_float(f2tf32(x));
}
__device__ __forceinline__ void mma_tf32(float* d, const uint32_t* a, const uint32_t* b) {
    asm volatile(
        "mma.sync.aligned.m16n8k8.row.col.f32.tf32.tf32.f32 "
        "{%0,%1,%2,%3},{%4,%5,%6,%7},{%8,%9},{%0,%1,%2,%3};\n"
        : "+f"(d[0]), "+f"(d[1]), "+f"(d[2]), "+f"(d[3])
        : "r"(a[0]), "r"(a[1]), "r"(a[2]), "r"(a[3]), "r"(b[0]), "r"(b[1]));
}
__device__ __forceinline__ void cp16(uint32_t s, const void* g) {
    asm volatile("cp.async.cg.shared.global [%0], [%1], 16;\n" :: "r"(s), "l"(g));
}
__device__ __forceinline__ void cp_commit() { asm volatile("cp.async.commit_group;\n"); }
template<int N> __device__ __forceinline__ void cp_wait() {
    asm volatile("cp.async.wait_group %0;\n" :: "n"(N));
}
// fast exp on FMA pipe; rel err ~2e-7
__device__ __forceinline__ float fast_exp(float x) {
    float y = fmaxf(x * 1.4426950408889634f, -126.f);
    float n = floorf(y);
    float f = y - n;
    float p =              1.8775767e-3f;
    p = fmaf(p, f, 8.9893397e-3f);
    p = fmaf(p, f, 5.5826318e-2f);
    p = fmaf(p, f, 2.4015361e-1f);
    p = fmaf(p, f, 6.9315308e-1f);
    p = fmaf(p, f, 9.9999994e-1f);
    return __int_as_float(__float_as_int(p) + (((int)n) << 23));
}

// ---------------- rmsnorm ----------------
__global__ void rmsnorm_k(const float* __restrict__ in, const float* __restrict__ g,
                          float* __restrict__ out) {
    int t = blockIdx.x;
    const float4* xi = (const float4*)(in + (size_t)t * DD);
    float4 v = xi[threadIdx.x];
    float ss = v.x*v.x + v.y*v.y + v.z*v.z + v.w*v.w;
    __shared__ float red[256];
    red[threadIdx.x] = ss;
    __syncthreads();
    for (int s = 128; s > 0; s >>= 1) {
        if (threadIdx.x < s) red[threadIdx.x] += red[threadIdx.x + s];
        __syncthreads();
    }
    float rms = rsqrtf(red[0] / (float)DD + 1e-6f);
    float4 gv = ((const float4*)g)[threadIdx.x];
    float4 o;
    o.x = v.x * gv.x * rms; o.y = v.y * gv.y * rms;
    o.z = v.z * gv.z * rms; o.w = v.w * gv.w * rms;
    ((float4*)(out + (size_t)t * DD))[threadIdx.x] = o;
}

// ---------------- tf32 GEMM: 128x128x16, 4-stage cp.async, single sync --------
#define GBM 128
#define GBN 128
#define GBK 16
#define ST    4
#define AROW  20
#define BROW  136
#define AW    (GBM*AROW)
#define BW    (GBK*BROW)
#define STW   (AW+BW)
#define GSMEM (ST*STW*4)

__global__ __launch_bounds__(256) void gemm_tf32(
    const float* __restrict__ A, const float* __restrict__ B, float* __restrict__ C,
    const float* __restrict__ addend, int M, int N, int K,
    long long sA, long long sB, long long sC, int relu)
{
    int e = blockIdx.z;
    A += (size_t)e * sA; B += (size_t)e * sB; C += (size_t)e * sC;

    extern __shared__ float smem[];
    uint32_t smem_base = (uint32_t)__cvta_generic_to_shared(smem);

    int tid  = threadIdx.x;
    int warp = tid >> 5, lane = tid & 31;
    int wm = (warp >> 1) * 32;
    int wn = (warp & 1) * 64;
    int r  = lane >> 2, c = lane & 3;

    int rowb = blockIdx.y * GBM, colb = blockIdx.x * GBN;

    int a_r0 = tid >> 2,           a_q0 = tid & 3;
    int a_r1 = (tid + 256) >> 2,   a_q1 = tid & 3;
    int b_k0 = tid >> 5,           b_q0 = tid & 31;
    int b_k1 = (tid + 256) >> 5,   b_q1 = tid & 31;

    float acc[2][8][4];
    #pragma unroll
    for (int mi = 0; mi < 2; mi++)
        #pragma unroll
        for (int ni = 0; ni < 8; ni++)
            #pragma unroll
            for (int q = 0; q < 4; q++) acc[mi][ni][q] = 0.f;

    int nk = K / GBK;

    auto issue = [&](int stage, int kt) {
        uint32_t sa = smem_base + stage * (STW * 4);
        uint32_t sb = sa + AW * 4;
        int k0 = kt * GBK;
        cp16(sa + (a_r0*AROW + a_q0*4)*4, A + (size_t)(rowb + a_r0)*K + k0 + a_q0*4);
        cp16(sa + (a_r1*AROW + a_q1*4)*4, A + (size_t)(rowb + a_r1)*K + k0 + a_q1*4);
        cp16(sb + (b_k0*BROW + b_q0*4)*4, B + (size_t)(k0 + b_k0)*N + colb + b_q0*4);
        cp16(sb + (b_k1*BROW + b_q1*4)*4, B + (size_t)(k0 + b_k1)*N + colb + b_q1*4);
    };

    int pre = (nk < ST-1) ? nk : ST-1;
    for (int s = 0; s < pre; s++) { issue(s, s); cp_commit(); }
    for (int s = pre; s < ST-1; s++) cp_commit();

    for (int kt = 0; kt < nk; kt++) {
        cp_wait<ST-2>();
        __syncthreads();

        int nx = kt + ST - 1;
        if (nx < nk) issue(nx % ST, nx);
        cp_commit();

        int stage = kt % ST;
        const uint32_t* As = (const uint32_t*)(smem + stage * STW);
        const uint32_t* Bs = (const uint32_t*)(smem + stage * STW + AW);

        #pragma unroll
        for (int ks = 0; ks < GBK; ks += 8) {
            uint32_t af[2][4];
            #pragma unroll
            for (int mi = 0; mi < 2; mi++) {
                int m = wm + mi * 16 + r;
                af[mi][0] = As[ m      *AROW + ks + c    ];
                af[mi][1] = As[(m + 8)*AROW + ks + c    ];
                af[mi][2] = As[ m      *AROW + ks + c + 4];
                af[mi][3] = As[(m + 8)*AROW + ks + c + 4];
            }
            #pragma unroll
            for (int ni = 0; ni < 8; ni++) {
                uint32_t bf[2];
                int n = wn + ni * 8 + r;
                bf[0] = Bs[(ks + c    )*BROW + n];
                bf[1] = Bs[(ks + c + 4)*BROW + n];
                mma_tf32(acc[0][ni], af[0], bf);
                mma_tf32(acc[1][ni], af[1], bf);
            }
        }
    }

    #pragma unroll
    for (int mi = 0; mi < 2; mi++) {
        #pragma unroll
        for (int ni = 0; ni < 8; ni++) {
            int row = rowb + wm + mi * 16 + r;
            int col = colb + wn + ni * 8 + 2 * c;
            size_t i0 = (size_t)row * N + col;
            size_t i1 = (size_t)(row + 8) * N + col;
            float2 v0 = make_float2(acc[mi][ni][0], acc[mi][ni][1]);
            float2 v1 = make_float2(acc[mi][ni][2], acc[mi][ni][3]);
            if (addend) {
                float2 d0 = *(const float2*)(addend + i0);
                float2 d1 = *(const float2*)(addend + i1);
                v0.x += d0.x; v0.y += d0.y; v1.x += d1.x; v1.y += d1.y;
            }
            if (relu) {
                v0.x = fmaxf(v0.x, 0.f); v0.y = fmaxf(v0.y, 0.f);
                v1.x = fmaxf(v1.x, 0.f); v1.y = fmaxf(v1.y, 0.f);
            }
            *(float2*)(C + i0) = v0;
            *(float2*)(C + i1) = v1;
        }
    }
}

// ---------------- RoPE + tf32 pre-round of q,k,v (in place) ----------------
__global__ void rope_k(float* __restrict__ qkv) {
    int t = blockIdx.x;
    int s = t % SS;
    for (int w = threadIdx.x; w < 1024; w += blockDim.x) {
        int which = w >> 9;
        int rem   = w & 511;
        int h     = rem >> 5;
        int i     = rem & 31;
        float theta = exp2f(-(float)i * 0.41524101186092030f);
        float fr = (float)s * theta;
        float cc, sn;
        __sincosf(fr, &sn, &cc);
        size_t base = (size_t)t * (3*DD) + (size_t)which * DD + h * HDIM + 2*i;
        float xr = qkv[base], xi = qkv[base+1];
        qkv[base]   = tf32r(xr*cc - xi*sn);
        qkv[base+1] = tf32r(xr*sn + xi*cc);
    }
    float4* vp = (float4*)(qkv + (size_t)t * (3*DD) + 2*DD);
    float4 v = vp[threadIdx.x];
    v.x = tf32r(v.x); v.y = tf32r(v.y); v.z = tf32r(v.z); v.w = tf32r(v.w);
    vp[threadIdx.x] = v;
}

// ---------------- tensor-core flash attention: 128 q/block, 8 warps ----------
// smem words: Q/P union 8704 | K0 4352 | K1 4352 | V0 4352 | V1 4352 = 26112
#define QP_W   8704
#define AT_SMEM ((QP_W + 4*4352) * 4)

__global__ __launch_bounds__(256) void attn_tc(const float* __restrict__ qkv,
                                               float* __restrict__ out) {
    extern __shared__ uint32_t sm[];
    uint32_t* Qs = sm;
    uint32_t smem_base = (uint32_t)__cvta_generic_to_shared(sm);

    int qt = gridDim.x - 1 - blockIdx.x;     // longest blocks first
    int bh = blockIdx.y;
    int b = bh >> 4, h = bh & 15;
    int tid = threadIdx.x, warp = tid >> 5, lane = tid & 31;
    int r = lane >> 2, c = lane & 3;
    int qb = qt * 128;
    const size_t RS = 3 * DD;
    const float scale = 0.125f;

    auto issue = [&](int st, int kt) {
        uint32_t kbase = smem_base + (QP_W + st*4352) * 4;
        uint32_t vbase = smem_base + (QP_W + 8704 + st*4352) * 4;
        const float* src = qkv + (size_t)(b*SS + kt*64) * RS + h*HDIM;
        #pragma unroll
        for (int u = tid; u < 1024; u += 256) {
            int row = u >> 4, q = (u & 15) * 4;
            size_t off = (size_t)row * RS + q;
            cp16(kbase + (row*68 + q)*4, src + DD   + off);
            cp16(vbase + (row*68 + q)*4, src + 2*DD + off);
        }
    };
    issue(0, 0);
    cp_commit();

    // ---- stage Q tile transposed [64 dims][132 pitch], scaled (pre-rounded) ----
    for (int u = tid; u < 2048; u += 256) {
        int row = u >> 4, d4 = (u & 15) * 4;
        float4 v = *(const float4*)(qkv + (size_t)(b*SS + qb + row) * RS + h*HDIM + d4);
        Qs[(d4+0)*132 + row] = __float_as_uint(v.x * scale);
        Qs[(d4+1)*132 + row] = __float_as_uint(v.y * scale);
        Qs[(d4+2)*132 + row] = __float_as_uint(v.z * scale);
        Qs[(d4+3)*132 + row] = __float_as_uint(v.w * scale);
    }
    __syncthreads();

    int mb = warp * 16;
    uint32_t qf[8][4];
    #pragma unroll
    for (int ks = 0; ks < 8; ks++) {
        int k0 = ks * 8;
        qf[ks][0] = Qs[(k0 + c    )*132 + mb + r];
        qf[ks][1] = Qs[(k0 + c    )*132 + mb + r + 8];
        qf[ks][2] = Qs[(k0 + c + 4)*132 + mb + r];
        qf[ks][3] = Qs[(k0 + c + 4)*132 + mb + r + 8];
    }

    uint32_t* Ps = Qs + warp * 1088;     // per-warp [64 keys][17]

    float oacc[8][4];
    #pragma unroll
    for (int ni = 0; ni < 8; ni++)
        #pragma unroll
        for (int q = 0; q < 4; q++) oacc[ni][q] = 0.f;
    float m0 = -INFINITY, m1 = -INFINITY, l0 = 0.f, l1 = 0.f;

    int row0 = qb + mb + r, row1 = row0 + 8;
    int nt = qt * 2 + 2;

    for (int kt = 0; kt < nt; kt++) {
        __syncthreads();                   // prior compute on overwritten stage done
        if (kt + 1 < nt) issue((kt + 1) & 1, kt + 1);
        cp_commit();
        cp_wait<1>();
        __syncthreads();                   // tile kt visible

        const uint32_t* Kst = sm + QP_W        + (kt & 1) * 4352;
        const uint32_t* Vst = sm + QP_W + 8704 + (kt & 1) * 4352;

        // ---- S = Q K^T ----
        float s[8][4];
        #pragma unroll
        for (int ni = 0; ni < 8; ni++) {
            float sa[4] = {0.f, 0.f, 0.f, 0.f};
            const uint32_t* kr = Kst + (ni*8 + r) * 68;
            #pragma unroll
            for (int ks = 0; ks < 8; ks++) {
                uint32_t bf[2];
                bf[0] = kr[ks*8 + c];
                bf[1] = kr[ks*8 + c + 4];
                mma_tf32(sa, qf[ks], bf);
            }
            s[ni][0] = sa[0]; s[ni][1] = sa[1]; s[ni][2] = sa[2]; s[ni][3] = sa[3];
        }

        // ---- causal mask (per-warp: only tiles crossing this warp's rows) ----
        int kbase = kt * 64;
        if (kbase + 63 > qb + mb) {
            #pragma unroll
            for (int ni = 0; ni < 8; ni++) {
                int col = kbase + ni*8 + 2*c;
                if (col     > row0) s[ni][0] = -1e30f;
                if (col + 1 > row0) s[ni][1] = -1e30f;
                if (col     > row1) s[ni][2] = -1e30f;
                if (col + 1 > row1) s[ni][3] = -1e30f;
            }
        }

        float mx0 = -1e30f, mx1 = -1e30f;
        #pragma unroll
        for (int ni = 0; ni < 8; ni++) {
            mx0 = fmaxf(mx0, fmaxf(s[ni][0], s[ni][1]));
            mx1 = fmaxf(mx1, fmaxf(s[ni][2], s[ni][3]));
        }
        mx0 = fmaxf(mx0, __shfl_xor_sync(0xffffffff, mx0, 1));
        mx0 = fmaxf(mx0, __shfl_xor_sync(0xffffffff, mx0, 2));
        mx1 = fmaxf(mx1, __shfl_xor_sync(0xffffffff, mx1, 1));
        mx1 = fmaxf(mx1, __shfl_xor_sync(0xffffffff, mx1, 2));
        float mn0 = fmaxf(m0, mx0), mn1 = fmaxf(m1, mx1);
        float cor0 = fast_exp(m0 - mn0), cor1 = fast_exp(m1 - mn1);
        m0 = mn0; m1 = mn1;

        float ls0 = 0.f, ls1 = 0.f;
        #pragma unroll
        for (int ni = 0; ni < 8; ni++) {
            float p0 = fast_exp(s[ni][0] - mn0);
            float p1 = fast_exp(s[ni][1] - mn0);
            float p2 = fast_exp(s[ni][2] - mn1);
            float p3 = fast_exp(s[ni][3] - mn1);
            ls0 += p0 + p1; ls1 += p2 + p3;
            int kc = ni*8 + 2*c;
            Ps[(kc    )*17 + r    ] = f2tf32(p0);
            Ps[(kc + 1)*17 + r    ] = f2tf32(p1);
            Ps[(kc    )*17 + r + 8] = f2tf32(p2);
            Ps[(kc + 1)*17 + r + 8] = f2tf32(p3);
        }
        ls0 += __shfl_xor_sync(0xffffffff, ls0, 1);
        ls0 += __shfl_xor_sync(0xffffffff, ls0, 2);
        ls1 += __shfl_xor_sync(0xffffffff, ls1, 1);
        ls1 += __shfl_xor_sync(0xffffffff, ls1, 2);
        l0 = l0 * cor0 + ls0;
        l1 = l1 * cor1 + ls1;

        #pragma unroll
        for (int ni = 0; ni < 8; ni++) {
            oacc[ni][0] *= cor0; oacc[ni][1] *= cor0;
            oacc[ni][2] *= cor1; oacc[ni][3] *= cor1;
        }
        __syncwarp();

        #pragma unroll
        for (int ks = 0; ks < 8; ks++) {
            int k0 = ks * 8;
            uint32_t af[4];
            af[0] = Ps[(k0 + c    )*17 + r];
            af[1] = Ps[(k0 + c    )*17 + r + 8];
            af[2] = Ps[(k0 + c + 4)*17 + r];
            af[3] = Ps[(k0 + c + 4)*17 + r + 8];
            #pragma unroll
            for (int ni = 0; ni < 8; ni++) {
                uint32_t bf[2];
                bf[0] = Vst[(k0 + c    )*68 + ni*8 + r];
                bf[1] = Vst[(k0 + c + 4)*68 + ni*8 + r];
                mma_tf32(oacc[ni], af, bf);
            }
        }
        __syncwarp();
    }

    float inv0 = 1.f / l0, inv1 = 1.f / l1;
    #pragma unroll
    for (int ni = 0; ni < 8; ni++) {
        int col = h*HDIM + ni*8 + 2*c;
        *(float2*)(out + (size_t)(b*SS + row0) * DD + col) =
            make_float2(oacc[ni][0]*inv0, oacc[ni][1]*inv0);
        *(float2*)(out + (size_t)(b*SS + row1) * DD + col) =
            make_float2(oacc[ni][2]*inv1, oacc[ni][3]*inv1);
    }
}

// ---------------- router ----------------
__global__ void router_k(const float* __restrict__ xn, const float* __restrict__ wr,
                         int* __restrict__ fe, float* __restrict__ fg) {
    int t = blockIdx.x;
    int lane = threadIdx.x & 31, w = threadIdx.x >> 5;
    const float* xr = xn + (size_t)t * DD;
    float p = 0.f;
    for (int d = lane; d < DD; d += 32) p += xr[d] * wr[(size_t)d * NE + w];
    #pragma unroll
    for (int o = 16; o > 0; o >>= 1) p += __shfl_xor_sync(0xffffffff, p, o);
    __shared__ float lg[NE];
    if (lane == 0) lg[w] = p;
    __syncthreads();
    if (threadIdx.x == 0) {
        float mx = lg[0];
        for (int e = 1; e < NE; e++) mx = fmaxf(mx, lg[e]);
        float pr[NE], sum = 0.f;
        for (int e = 0; e < NE; e++) { pr[e] = expf(lg[e] - mx); sum += pr[e]; }
        float inv = 1.f / sum;
        int e1 = 0; float v1 = pr[0];
        for (int e = 1; e < NE; e++) if (pr[e] > v1) { v1 = pr[e]; e1 = e; }
        int e2 = -1; float v2 = -INFINITY;
        for (int e = 0; e < NE; e++) {
            if (e == e1) continue;
            if (pr[e] > v2) { v2 = pr[e]; e2 = e; }
        }
        fe[2*t]   = e1; fg[2*t]   = v1 * inv;
        fe[2*t+1] = e2; fg[2*t+1] = v2 * inv;
    }
}

__global__ void zero_k(int* cnt) { if (threadIdx.x < NE) cnt[threadIdx.x] = 0; }

__global__ void assign_k(const int* __restrict__ fe, const float* __restrict__ fg,
                         int* __restrict__ cnt, int* __restrict__ esl,
                         float* __restrict__ egt) {
    int s = blockIdx.x * blockDim.x + threadIdx.x;
    if (s >= NS) return;
    int e = fe[s];
    int p = atomicAdd(&cnt[e], 1);
    esl[e*NS + p] = s;
    egt[e*NS + p] = fg[s];
}

__global__ void select_k(const int* __restrict__ cnt, const int* __restrict__ esl,
                         const float* __restrict__ egt, int* __restrict__ dtok,
                         int* __restrict__ srow) {
    int e = blockIdx.x;
    int n = cnt[e];
    const int*   sl = esl + e*NS;
    const float* gt = egt + e*NS;
    for (int i = threadIdx.x; i < n; i += blockDim.x) {
        float gi = gt[i]; int si = sl[i];
        int rank = 0;
        for (int j = 0; j < n; j++) {
            float gj = gt[j]; int sj = sl[j];
            rank += (gj > gi) || (gj == gi && sj < si);
        }
        if (rank < CAPN) {
            dtok[e*CAPN + rank] = si >> 1;
            srow[si] = e*CAPN + rank;
        } else srow[si] = -1;
    }
    for (int rr = n + threadIdx.x; rr < CAPN; rr += blockDim.x) dtok[e*CAPN + rr] = 0;
}

__global__ void gather_k(const int* __restrict__ dtok, const float* __restrict__ xn2,
                         float* __restrict__ xe) {
    int R = blockIdx.x;
    int tok = dtok[R];
    ((float4*)(xe + (size_t)R * DD))[threadIdx.x] =
        ((const float4*)(xn2 + (size_t)tok * DD))[threadIdx.x];
}

__global__ void combine_k(const float* __restrict__ x1, const float* __restrict__ ye,
                          const int* __restrict__ srow, const float* __restrict__ fg,
                          float* __restrict__ out) {
    int t = blockIdx.x;
    float4 o = ((const float4*)(x1 + (size_t)t * DD))[threadIdx.x];
    #pragma unroll
    for (int k = 0; k < 2; k++) {
        int s = 2*t + k;
        int rr = srow[s];
        if (rr >= 0) {
            float gg = fg[s];
            float4 y = ((const float4*)(ye + (size_t)rr * DD))[threadIdx.x];
            o.x += gg*y.x; o.y += gg*y.y; o.z += gg*y.z; o.w += gg*y.w;
        }
    }
    ((float4*)(out + (size_t)t * DD))[threadIdx.x] = o;
}

// ---------------- host ----------------
extern "C" void kernel_launch(void* const* d_in, const int* in_sizes, int n_in,
                              void* d_out, int out_size) {
    const float* x        = (const float*)d_in[0];
    const float* g1       = (const float*)d_in[1];
    const float* w_qkv    = (const float*)d_in[2];
    const float* w_o      = (const float*)d_in[3];
    const float* g2       = (const float*)d_in[4];
    const float* w_router = (const float*)d_in[5];
    const float* w1       = (const float*)d_in[6];
    const float* w2       = (const float*)d_in[7];
    float* out = (float*)d_out;

    float *xn, *qkv, *attn, *x1, *xn2, *fg, *egt, *xe, *h, *ye;
    int *fe, *cnt, *esl, *dtok, *srow;
    cudaGetSymbolAddress((void**)&xn,   g_xn);
    cudaGetSymbolAddress((void**)&qkv,  g_qkv);
    cudaGetSymbolAddress((void**)&attn, g_attn);
    cudaGetSymbolAddress((void**)&x1,   g_x1);
    cudaGetSymbolAddress((void**)&xn2,  g_xn2);
    cudaGetSymbolAddress((void**)&fe,   g_fe);
    cudaGetSymbolAddress((void**)&fg,   g_fg);
    cudaGetSymbolAddress((void**)&cnt,  g_cnt);
    cudaGetSymbolAddress((void**)&esl,  g_esl);
    cudaGetSymbolAddress((void**)&egt,  g_egt);
    cudaGetSymbolAddress((void**)&dtok, g_dtok);
    cudaGetSymbolAddress((void**)&srow, g_srow);
    cudaGetSymbolAddress((void**)&xe,   g_xe);
    cudaGetSymbolAddress((void**)&h,    g_h);
    cudaGetSymbolAddress((void**)&ye,   g_ye);

    static bool attr_set = false;
    if (!attr_set) {
        cudaFuncSetAttribute(attn_tc,   cudaFuncAttributeMaxDynamicSharedMemorySize, AT_SMEM);
        cudaFuncSetAttribute(gemm_tf32, cudaFuncAttributeMaxDynamicSharedMemorySize, GSMEM);
        attr_set = true;
    }

    // attention branch
    rmsnorm_k<<<TT, 256>>>(x, g1, xn);
    gemm_tf32<<<dim3(3*DD/GBN, TT/GBM, 1), 256, GSMEM>>>(xn, w_qkv, qkv, nullptr,
                                                         TT, 3*DD, DD, 0, 0, 0, 0);
    rope_k<<<TT, 256>>>(qkv);
    attn_tc<<<dim3(SS/128, BB*HH), 256, AT_SMEM>>>(qkv, attn);
    gemm_tf32<<<dim3(DD/GBN, TT/GBM, 1), 256, GSMEM>>>(attn, w_o, x1, x,
                                                       TT, DD, DD, 0, 0, 0, 0);

    // MoE branch
    rmsnorm_k<<<TT, 256>>>(x1, g2, xn2);
    router_k<<<TT, 256>>>(xn2, w_router, fe, fg);
    zero_k<<<1, 32>>>(cnt);
    assign_k<<<NS/256, 256>>>(fe, fg, cnt, esl, egt);
    select_k<<<NE, 512>>>(cnt, esl, egt, dtok, srow);
    gather_k<<<NE*CAPN, 256>>>(dtok, xn2, xe);
    gemm_tf32<<<dim3(FFND/GBN, CAPN/GBM, NE), 256, GSMEM>>>(xe, w1, h, nullptr,
        CAPN, FFND, DD, (long long)CAPN*DD, (long long)DD*FFND, (long long)CAPN*FFND, 1);
    gemm_tf32<<<dim3(DD/GBN, CAPN/GBM, NE), 256, GSMEM>>>(h, w2, ye, nullptr,
        CAPN, DD, FFND, (long long)CAPN*FFND, (long long)FFND*DD, (long long)CAPN*DD, 0);
    combine_k<<<TT, 256>>>(x1, ye, srow, fg, out);
}